// round 12
// baseline (speedup 1.0000x reference)
#include <cuda_runtime.h>
#include <cuda_bf16.h>

// LocalLoadBalancingLoss: B=65536, T=792, D=99, L=16.
// loss = mean_b[ var_{ddof=1}(u_b) + 0.5 * max(u_b) ], u = linkTraffic/(cap+1e-8)
//
// R11 = R8 (best: 16 rows, 512 thr, 4 blocks/SM) +
//  - release-scope atomic instead of __threadfence() (no per-block L1D IVALL,
//    CSR index lines stay L1-hot across blocks on the same SM)
//  - fixed-stride CSR of packed byte offsets, 4-aligned halves -> LDG.128
//    index loads (4 entries per chain-head)
//  - 16B cp.async for the dem tile

#define NUM_T 792
#define NUM_D 99
#define NUM_L 16
#define ROWS 16
#define THREADS 512
#define PST 793                 // odd float stride -> conflict-free LDS across rows
#define MAX_BLOCKS 4096
#define SETUP_THREADS 800
#define LSTRIDE 128             // CSR slots per link (len ~49.5 +- 7, safe)

__device__ unsigned g_poff[NUM_L * LSTRIDE];  // (pred_byte_off<<16)|dem_byte_off
__device__ int      g_len[NUM_L];
__device__ float    g_partials[MAX_BLOCKS];
__device__ unsigned g_done;

__device__ __forceinline__ void cpa4(unsigned dst, const float* src) {
    asm volatile("cp.async.ca.shared.global [%0], [%1], 4;" :: "r"(dst), "l"(src));
}
__device__ __forceinline__ void cpa16(unsigned dst, const float* src) {
    asm volatile("cp.async.cg.shared.global [%0], [%1], 16;" :: "r"(dst), "l"(src));
}

// ---------------------------------------------------------------------------
// Setup: fixed-stride link-sorted CSR of packed byte offsets.
// ---------------------------------------------------------------------------
__global__ void llb_setup_kernel(const int* __restrict__ t2l) {
    __shared__ int s_wcnt[25][NUM_L];

    const int tid  = threadIdx.x;       // 800 = 25 warps
    const int w    = tid >> 5;
    const int lane = tid & 31;
    const bool act = (tid < NUM_T);

    if (tid < 25 * NUM_L) ((int*)s_wcnt)[tid] = 0;

    const int l = act ? t2l[tid] : 0;
    const int val = act ? l : (100 + lane);     // idle lanes -> singleton groups
    __syncthreads();

    unsigned m = __match_any_sync(0xFFFFFFFFu, val);
    const int rank = __popc(m & ((1u << lane) - 1u));
    if (act && lane == (__ffs(m) - 1)) s_wcnt[w][l] = __popc(m);
    __syncthreads();

    if (tid < NUM_L) {
        int acc = 0;
        for (int ww = 0; ww < 25; ww++) {
            int c = s_wcnt[ww][tid];
            s_wcnt[ww][tid] = acc;               // exclusive prefix over warps
            acc += c;
        }
        g_len[tid] = acc;
    }
    __syncthreads();

    if (act) {
        unsigned pk = ((unsigned)(tid * 4) << 16) | (unsigned)((tid >> 3) * 4);
        g_poff[LSTRIDE * l + s_wcnt[w][l] + rank] = pk;
    }
}

// ---------------------------------------------------------------------------
// Main: 4096 blocks x 16 rows; warp = link, half-warp = segment half, lane = row.
// ---------------------------------------------------------------------------
__global__ __launch_bounds__(THREADS, 4)
void llb_main_kernel(const float* __restrict__ pred,
                     const float* __restrict__ dem,
                     const float* __restrict__ cap,
                     float* __restrict__ out,
                     float inv_batch) {
    extern __shared__ float smem[];
    float* sp = smem;                    // [16][793]
    float* sd = smem + ROWS * PST;       // [16][99]; later overlaid as su[16][17]
    __shared__ int sflag;

    const int tid  = threadIdx.x;
    const int w    = tid >> 5;           // link
    const int lane = tid & 31;
    const int part = lane >> 4;          // segment half
    const int r    = lane & 15;          // row

    // metadata early (overlaps staging)
    const int   len  = g_len[w];
    int len0 = (((len + 1) >> 1) + 3) & ~3;      // round half up to multiple of 4
    if (len0 > len) len0 = len;
    const int   mybeg = LSTRIDE * w + (part ? len0 : 0);
    const int   mycnt = part ? (len - len0) : len0;
    const float invc  = 1.0f / (cap[w] + 1e-8f);

    const long long tile = blockIdx.x;
    const float* gp = pred + tile * (ROWS * NUM_T);
    const float* gd = dem  + tile * (ROWS * NUM_D);
    const unsigned spA = (unsigned)__cvta_generic_to_shared(sp);
    const unsigned sdA = (unsigned)__cvta_generic_to_shared(sd);

    // ---- stage-in ----
    #pragma unroll
    for (int k = 0; k < 25; k++) {
        int i = tid + k * THREADS;
        if (i < ROWS * NUM_T) {
            int rr = (unsigned)i / NUM_T;        // smem idx = i + rr (stride 793)
            cpa4(spA + 4u * (unsigned)(i + rr), gp + i);
        }
    }
    if (tid < (ROWS * NUM_D) / 4)                // 1584 floats = 396 x 16B
        cpa16(sdA + 16u * (unsigned)tid, gd + 4 * tid);
    asm volatile("cp.async.commit_group;");
    asm volatile("cp.async.wait_group 0;");
    __syncthreads();

    // ---- phase B: half-warp walks its 4-aligned half-segment, lane = row ----
    const char* pr = (const char*)(sp + r * PST);
    const char* dm = (const char*)(sd + r * NUM_D);
    const uint4* ix4 = (const uint4*)(g_poff + mybeg);   // mybeg multiple of 4

    float s0 = 0.f, s1 = 0.f, s2 = 0.f, s3 = 0.f;
    int i = 0;
    for (; i + 3 < mycnt; i += 4) {
        uint4 p = __ldg(ix4 + (i >> 2));         // L1-hot LDG.128: 4 entries
        s0 += *(const float*)(pr + (p.x >> 16)) * *(const float*)(dm + (p.x & 0xFFFFu));
        s1 += *(const float*)(pr + (p.y >> 16)) * *(const float*)(dm + (p.y & 0xFFFFu));
        s2 += *(const float*)(pr + (p.z >> 16)) * *(const float*)(dm + (p.z & 0xFFFFu));
        s3 += *(const float*)(pr + (p.w >> 16)) * *(const float*)(dm + (p.w & 0xFFFFu));
    }
    for (; i < mycnt; i++) {                     // tail (< 4 entries)
        unsigned p = __ldg(g_poff + mybeg + i);
        s0 += *(const float*)(pr + (p >> 16)) * *(const float*)(dm + (p & 0xFFFFu));
    }
    float u = ((s0 + s1) + (s2 + s3)) * invc;
    u += __shfl_down_sync(0xFFFFFFFFu, u, 16);   // combine segment halves

    __syncthreads();                     // all sd reads done -> overlay su
    float* su = sd;                      // [16 links][17]
    if (part == 0) su[w * 17 + r] = u;
    __syncthreads();

    // ---- per-row stats: warp 0, lanes 0-15 (row = lane) ----
    float pv = 0.f;
    if (w == 0 && part == 0) {
        float sum = 0.f, mx = -1e30f;
        #pragma unroll
        for (int l = 0; l < NUM_L; l++) {
            float x = su[l * 17 + r];
            sum += x;
            mx = fmaxf(mx, x);
        }
        const float mean = sum * (1.0f / NUM_L);
        float var = 0.f;
        #pragma unroll
        for (int l = 0; l < NUM_L; l++) {
            float d = su[l * 17 + r] - mean;
            var += d * d;
        }
        var *= (1.0f / (NUM_L - 1));             // ddof = 1
        pv = var + 0.5f * mx;
        #pragma unroll
        for (int o = 8; o > 0; o >>= 1)
            pv += __shfl_down_sync(0x0000FFFFu, pv, o);
    }
    if (tid == 0) g_partials[blockIdx.x] = pv;

    // ---- fused deterministic reduction; release atom avoids L1D invalidate ----
    if (tid == 0) {
        unsigned n;
        asm volatile("atom.release.gpu.global.add.u32 %0, [%1], 1;"
                     : "=r"(n) : "l"(&g_done) : "memory");
        sflag = (n == (unsigned)(gridDim.x - 1)) ? 1 : 0;
    }
    __syncthreads();
    if (sflag) {
        asm volatile("fence.acq_rel.gpu;" ::: "memory");   // once, winner only
        float v = 0.f;
        #pragma unroll
        for (int k = 0; k < MAX_BLOCKS / THREADS; k++)
            v += g_partials[tid + k * THREADS];  // fixed order per thread
        float* rb = sp;                          // reuse smem
        rb[tid] = v;
        __syncthreads();
        #pragma unroll
        for (int s = THREADS / 2; s > 0; s >>= 1) {
            if (tid < s) rb[tid] += rb[tid + s]; // fixed pairing -> deterministic
            __syncthreads();
        }
        if (tid == 0) {
            out[0] = rb[0] * inv_batch;
            g_done = 0;                          // reset for next graph replay
        }
    }
}

extern "C" void kernel_launch(void* const* d_in, const int* in_sizes, int n_in,
                              void* d_out, int out_size) {
    const float* pred = (const float*)d_in[0];   // [B, 792]
    const float* dem  = (const float*)d_in[1];   // [B, 99]
    const int*   t2l  = (const int*)d_in[2];     // [792]
    const float* cap  = (const float*)d_in[3];   // [16]
    float* out = (float*)d_out;

    const int B = in_sizes[1] / NUM_D;           // 65536
    const int ntiles = B / ROWS;                 // 4096

    static bool attr_set = false;
    const int smem_bytes = (ROWS * PST + ROWS * NUM_D) * (int)sizeof(float); // 57088
    if (!attr_set) {
        cudaFuncSetAttribute(llb_main_kernel,
                             cudaFuncAttributeMaxDynamicSharedMemorySize, smem_bytes);
        attr_set = true;
    }

    llb_setup_kernel<<<1, SETUP_THREADS>>>(t2l);
    llb_main_kernel<<<ntiles, THREADS, smem_bytes>>>(pred, dem, cap, out,
                                                     1.0f / (float)B);
}

// round 13
// speedup vs baseline: 1.4131x; 1.4131x over previous
#include <cuda_runtime.h>
#include <cuda_bf16.h>

// LocalLoadBalancingLoss: B=65536, T=792, D=99, L=16.
// loss = mean_b[ var_{ddof=1}(u_b) + 0.5 * max(u_b) ], u = linkTraffic/(cap+1e-8)
//
// R13 = R8 (best: 16 rows, 512 thr, 4 blocks/SM, warp=link, half-warp=segment
// half, lane=row) with ONE change: fixed-stride CSR + even-aligned half-segments
// so phase B consumes indices as u32 pairs (one LDG per 2 entries, 4 FMA chains).

#define NUM_T 792
#define NUM_D 99
#define NUM_L 16
#define ROWS 16
#define THREADS 512
#define PST 793                 // odd stride -> conflict-free LDS across rows
#define MAX_BLOCKS 4096
#define SETUP_THREADS 800
#define LSTRIDE 128             // u16 CSR slots per link (len ~49.5, safe), 256B-aligned

__device__ unsigned short g_pidx16[NUM_L * LSTRIDE];  // tunnel ids, per-link slabs
__device__ int   g_len[NUM_L];
__device__ float g_partials[MAX_BLOCKS];
__device__ unsigned int g_done;

__device__ __forceinline__ void cpa4(unsigned dst, const float* src) {
    asm volatile("cp.async.ca.shared.global [%0], [%1], 4;" :: "r"(dst), "l"(src));
}

// ---------------------------------------------------------------------------
// Setup: fixed-stride link-sorted CSR (u16 tunnel ids), deterministic rank via
// __match_any_sync + per-link prefix over warps. Same as R8 apart from layout.
// ---------------------------------------------------------------------------
__global__ void llb_setup_kernel(const int* __restrict__ t2l) {
    __shared__ int s_wcnt[25][NUM_L];

    const int tid  = threadIdx.x;       // 800 = 25 warps
    const int w    = tid >> 5;
    const int lane = tid & 31;
    const bool act = (tid < NUM_T);

    if (tid < 25 * NUM_L) ((int*)s_wcnt)[tid] = 0;

    const int l = act ? t2l[tid] : 0;
    const int val = act ? l : (100 + lane);     // idle lanes -> singleton groups
    __syncthreads();

    unsigned m = __match_any_sync(0xFFFFFFFFu, val);
    const int rank = __popc(m & ((1u << lane) - 1u));
    if (act && lane == (__ffs(m) - 1)) s_wcnt[w][l] = __popc(m);
    __syncthreads();

    if (tid < NUM_L) {
        int acc = 0;
        for (int ww = 0; ww < 25; ww++) {
            int c = s_wcnt[ww][tid];
            s_wcnt[ww][tid] = acc;               // exclusive prefix over warps
            acc += c;
        }
        g_len[tid] = acc;
    }
    __syncthreads();

    if (act) g_pidx16[LSTRIDE * l + s_wcnt[w][l] + rank] = (unsigned short)tid;
    // zero the padding slots so stray reads are harmless (never accumulated)
    if (tid < NUM_L) {
        int base = LSTRIDE * tid;
        for (int k = g_len[tid]; k < LSTRIDE; k++) g_pidx16[base + k] = 0;
    }
}

// ---------------------------------------------------------------------------
// Main: 4096 blocks x 16 rows; warp = link, half-warp = segment half, lane = row.
// ---------------------------------------------------------------------------
__global__ __launch_bounds__(THREADS, 4)
void llb_main_kernel(const float* __restrict__ pred,
                     const float* __restrict__ dem,
                     const float* __restrict__ cap,
                     float* __restrict__ out,
                     float inv_batch) {
    extern __shared__ float smem[];
    float* sp = smem;                    // [16][793]
    float* sd = smem + ROWS * PST;       // [16][99]; later overlaid as su[16][17]
    __shared__ int sflag;

    const int tid  = threadIdx.x;
    const int w    = tid >> 5;           // link
    const int lane = tid & 31;
    const int part = lane >> 4;          // segment half
    const int r    = lane & 15;          // row

    // metadata early (L2 latency overlaps staging)
    const int   len  = g_len[w];
    int len0 = (((len + 1) >> 1) + 1) & ~1;      // half, rounded up to even
    if (len0 > len) len0 = len;
    const int   mybeg = LSTRIDE * w + (part ? len0 : 0);  // part0 start even
    const int   mycnt = part ? (len - len0) : len0;
    const float invc  = 1.0f / (cap[w] + 1e-8f);

    const long long tile = blockIdx.x;
    const float* gp = pred + tile * (ROWS * NUM_T);
    const float* gd = dem  + tile * (ROWS * NUM_D);
    const unsigned spA = (unsigned)__cvta_generic_to_shared(sp);
    const unsigned sdA = (unsigned)__cvta_generic_to_shared(sd);

    // ---- stage-in (identical to R8) ----
    #pragma unroll
    for (int k = 0; k < 25; k++) {
        int i = tid + k * THREADS;
        if (i < ROWS * NUM_T) {
            int rr = (unsigned)i / NUM_T;        // smem idx = i + rr (stride 793)
            cpa4(spA + 4u * (unsigned)(i + rr), gp + i);
        }
    }
    #pragma unroll
    for (int k = 0; k < 4; k++) {
        int i = tid + k * THREADS;
        if (i < ROWS * NUM_D) cpa4(sdA + 4u * (unsigned)i, gd + i);
    }
    asm volatile("cp.async.commit_group;");
    asm volatile("cp.async.wait_group 0;");
    __syncthreads();

    // ---- phase B: half-warp walks its half-segment, lane = row ----
    // Indices consumed as u32 pairs (two u16 each): one LDG per 2 entries.
    const float* pr = sp + r * PST;
    const float* dm = sd + r * NUM_D;
    const unsigned* ix2 = (const unsigned*)(g_pidx16 + (mybeg & ~1));
    const int odd = mybeg & 1;           // part1 may start mid-pair

    float s0 = 0.f, s1 = 0.f, s2 = 0.f, s3 = 0.f;
    int i = 0;                           // entry index within my half-segment
    if (odd && mycnt > 0) {              // leading single (high half of pair 0)
        unsigned p = __ldg(ix2);
        int t = p >> 16;
        s0 += pr[t] * dm[t >> 3];
        i = 1;
    }
    // now (mybeg + i) is even; pair index = (odd + i) >> 1 ... simplified below
    int pairbase = (odd + 1) >> 1;       // 0 if aligned, 1 if we consumed pair 0
    for (; i + 3 < mycnt; i += 4) {
        unsigned pa = __ldg(ix2 + pairbase + ((i - odd * 0) >> 1) + (odd ? 0 : 0));
        unsigned pb = __ldg(ix2 + pairbase + (i >> 1) + (odd ? 0 : 0) + 1);
        // recompute cleanly: entries i..i+3 live in pairs (mybeg+i)/2 relative
        (void)pa; (void)pb;
        unsigned q0 = __ldg((const unsigned*)(g_pidx16 + mybeg + i));
        unsigned q1 = __ldg((const unsigned*)(g_pidx16 + mybeg + i + 2));
        int t0 = q0 & 0xFFFFu, t1 = q0 >> 16;
        int t2 = q1 & 0xFFFFu, t3 = q1 >> 16;
        s0 += pr[t0] * dm[t0 >> 3];
        s1 += pr[t1] * dm[t1 >> 3];
        s2 += pr[t2] * dm[t2 >> 3];
        s3 += pr[t3] * dm[t3 >> 3];
    }
    for (; i < mycnt; i++) {             // tail 0..3 entries
        int t = __ldg(g_pidx16 + mybeg + i);
        s0 += pr[t] * dm[t >> 3];
    }
    float u = ((s0 + s1) + (s2 + s3)) * invc;
    u += __shfl_down_sync(0xFFFFFFFFu, u, 16);   // combine segment halves

    __syncthreads();                     // all sd reads done -> overlay su
    float* su = sd;                      // [16 links][17]
    if (part == 0) su[w * 17 + r] = u;
    __syncthreads();

    // ---- per-row stats: warp 0, lanes 0-15 (row = lane) ----
    float pv = 0.f;
    if (w == 0 && part == 0) {
        float sum = 0.f, mx = -1e30f;
        #pragma unroll
        for (int l = 0; l < NUM_L; l++) {
            float x = su[l * 17 + r];
            sum += x;
            mx = fmaxf(mx, x);
        }
        const float mean = sum * (1.0f / NUM_L);
        float var = 0.f;
        #pragma unroll
        for (int l = 0; l < NUM_L; l++) {
            float d = su[l * 17 + r] - mean;
            var += d * d;
        }
        var *= (1.0f / (NUM_L - 1));             // ddof = 1
        pv = var + 0.5f * mx;
        #pragma unroll
        for (int o = 8; o > 0; o >>= 1)
            pv += __shfl_down_sync(0x0000FFFFu, pv, o);
    }
    if (tid == 0) g_partials[blockIdx.x] = pv;

    // ---- fused deterministic reduction (identical to R8) ----
    __threadfence();
    if (tid == 0) {
        unsigned n = atomicAdd(&g_done, 1u);
        sflag = (n == (unsigned)(gridDim.x - 1)) ? 1 : 0;
    }
    __syncthreads();
    if (sflag) {
        __threadfence();
        float v = 0.f;
        #pragma unroll
        for (int k = 0; k < MAX_BLOCKS / THREADS; k++)
            v += g_partials[tid + k * THREADS];  // fixed order per thread
        float* rb = sp;                          // reuse smem
        rb[tid] = v;
        __syncthreads();
        #pragma unroll
        for (int s = THREADS / 2; s > 0; s >>= 1) {
            if (tid < s) rb[tid] += rb[tid + s]; // fixed pairing -> deterministic
            __syncthreads();
        }
        if (tid == 0) {
            out[0] = rb[0] * inv_batch;
            g_done = 0;                          // reset for next graph replay
        }
    }
}

extern "C" void kernel_launch(void* const* d_in, const int* in_sizes, int n_in,
                              void* d_out, int out_size) {
    const float* pred = (const float*)d_in[0];   // [B, 792]
    const float* dem  = (const float*)d_in[1];   // [B, 99]
    const int*   t2l  = (const int*)d_in[2];     // [792]
    const float* cap  = (const float*)d_in[3];   // [16]
    float* out = (float*)d_out;

    const int B = in_sizes[1] / NUM_D;           // 65536
    const int ntiles = B / ROWS;                 // 4096

    static bool attr_set = false;
    const int smem_bytes = (ROWS * PST + ROWS * NUM_D) * (int)sizeof(float); // 57088
    if (!attr_set) {
        cudaFuncSetAttribute(llb_main_kernel,
                             cudaFuncAttributeMaxDynamicSharedMemorySize, smem_bytes);
        attr_set = true;
    }

    llb_setup_kernel<<<1, SETUP_THREADS>>>(t2l);
    llb_main_kernel<<<ntiles, THREADS, smem_bytes>>>(pred, dem, cap, out,
                                                     1.0f / (float)B);
}